// round 13
// baseline (speedup 1.0000x reference)
#include <cuda_runtime.h>
#include <cuda_bf16.h>
#include <math.h>

#define BB 128
#define TT 256
#define HH 768
#define KK 64

typedef unsigned long long u64t;

__device__ float g_emis[BB * TT * KK];   // emissions scratch, 8 MB

// ---- packed f32x2 helpers ------------------------------------------------
__device__ __forceinline__ u64t ffma2(u64t a, u64t b, u64t c) {
    u64t d;
    asm("fma.rn.f32x2 %0, %1, %2, %3;" : "=l"(d) : "l"(a), "l"(b), "l"(c));
    return d;
}
__device__ __forceinline__ u64t pack2(float lo, float hi) {
    u64t d;
    unsigned a = __float_as_uint(lo), b = __float_as_uint(hi);
    asm("mov.b64 %0, {%1, %2};" : "=l"(d) : "r"(a), "r"(b));
    return d;
}
__device__ __forceinline__ void unpack2(u64t v, float* lo, float* hi) {
    unsigned a, b;
    asm("mov.b64 {%0, %1}, %2;" : "=r"(a), "=r"(b) : "l"(v));
    *lo = __uint_as_float(a);
    *hi = __uint_as_float(b);
}
__device__ __forceinline__ void barx(int id, int n) {
    asm volatile("bar.sync %0, %1;" :: "r"(id), "r"(n) : "memory");
}

// ---------------------------------------------------------------------------
// Kernel 1: emissions = hidden @ W + b (round-8 verbatim; ~FFMA2 floor)
// ---------------------------------------------------------------------------
__global__ __launch_bounds__(256) void gemm_emis_kernel(
    const float* __restrict__ A,
    const float* __restrict__ Wm,
    const float* __restrict__ bias)
{
    __shared__ float As[16][132];
    __shared__ float Bs[16][64];

    const int tid = threadIdx.x;
    const int m0 = blockIdx.x * 128;
    const int ty = tid >> 4;
    const int tx = tid & 15;

    u64t acc2[4][4];
#pragma unroll
    for (int rp = 0; rp < 4; rp++)
#pragma unroll
        for (int c = 0; c < 4; c++) acc2[rp][c] = 0ull;

    const int arow0 = (tid) >> 2,       ac40 = (tid) & 3;
    const int arow1 = (tid + 256) >> 2, ac41 = (tid + 256) & 3;
    const int brow = tid >> 4, bc4 = tid & 15;

    float4 aReg0 = *(const float4*)&A[(size_t)(m0 + arow0) * HH + ac40 * 4];
    float4 aReg1 = *(const float4*)&A[(size_t)(m0 + arow1) * HH + ac41 * 4];
    float4 bReg  = *(const float4*)&Wm[(size_t)(brow) * KK + bc4 * 4];

    for (int kt = 0; kt < HH; kt += 16) {
        As[ac40 * 4 + 0][arow0] = aReg0.x;
        As[ac40 * 4 + 1][arow0] = aReg0.y;
        As[ac40 * 4 + 2][arow0] = aReg0.z;
        As[ac40 * 4 + 3][arow0] = aReg0.w;
        As[ac41 * 4 + 0][arow1] = aReg1.x;
        As[ac41 * 4 + 1][arow1] = aReg1.y;
        As[ac41 * 4 + 2][arow1] = aReg1.z;
        As[ac41 * 4 + 3][arow1] = aReg1.w;
        *(float4*)&Bs[brow][bc4 * 4] = bReg;
        __syncthreads();

        if (kt + 16 < HH) {
            aReg0 = *(const float4*)&A[(size_t)(m0 + arow0) * HH + kt + 16 + ac40 * 4];
            aReg1 = *(const float4*)&A[(size_t)(m0 + arow1) * HH + kt + 16 + ac41 * 4];
            bReg  = *(const float4*)&Wm[(size_t)(kt + 16 + brow) * KK + bc4 * 4];
        }

#pragma unroll
        for (int kk = 0; kk < 16; kk++) {
            const u64t* ap = (const u64t*)&As[kk][ty * 8];
            u64t a2[4];
#pragma unroll
            for (int rp = 0; rp < 4; rp++) a2[rp] = ap[rp];
            float4 bv = *(const float4*)&Bs[kk][tx * 4];
            u64t bd[4];
            bd[0] = pack2(bv.x, bv.x);
            bd[1] = pack2(bv.y, bv.y);
            bd[2] = pack2(bv.z, bv.z);
            bd[3] = pack2(bv.w, bv.w);
#pragma unroll
            for (int rp = 0; rp < 4; rp++)
#pragma unroll
                for (int c = 0; c < 4; c++)
                    acc2[rp][c] = ffma2(a2[rp], bd[c], acc2[rp][c]);
        }
        __syncthreads();
    }

    float4 bb = *(const float4*)&bias[tx * 4];
    const float bbv[4] = {bb.x, bb.y, bb.z, bb.w};
#pragma unroll
    for (int rp = 0; rp < 4; rp++) {
        float o0[4], o1[4];
#pragma unroll
        for (int c = 0; c < 4; c++) {
            float lo, hi;
            unpack2(acc2[rp][c], &lo, &hi);
            o0[c] = lo + bbv[c];
            o1[c] = hi + bbv[c];
        }
        int row = m0 + ty * 8 + 2 * rp;
        *(float4*)&g_emis[(size_t)row * KK + tx * 4]       = make_float4(o0[0], o0[1], o0[2], o0[3]);
        *(float4*)&g_emis[(size_t)(row + 1) * KK + tx * 4] = make_float4(o1[0], o1[1], o1[2], o1[3]);
    }
}

// Per-group smem layout (bytes)
#define GOFF_V     0        // 3*64*4  = 768
#define GOFF_P     768      // 2*64*4  = 512  -> 1280
#define GOFF_RED   1280     // 8*4     = 32   -> 1312
#define GOFF_MISC  1312     // 16             -> 1328
#define GOFF_PATH  1328     // 256*4   = 1024 -> 2352
#define GOFF_BP    2352     // 255*64  = 16320-> 18672
#define GROUP_BYTES 18688
#define OFF_TT     (2 * GROUP_BYTES)            // 64*68*4 = 17408
#define SMEM_BYTES (OFF_TT + 17408)             // 54784

// ---------------------------------------------------------------------------
// Kernel 2: CRF, TWO batches per block. grid=64, block=512 (one wave):
//   group g = tid>>8 handles batch 2*bid+g; within a group (lt = tid&255):
//     lt 0..127  : Viterbi (round-8 verbatim), bar.sync 1+2g, 128
//     lt 128..255: forward+seq_score (round-8 verbatim), bar.sync 2+2g, 128
// Four independent chains per SM fill each other's latency stalls.
// s_tt shared across groups (identical duplicate writes are benign).
// ---------------------------------------------------------------------------
__global__ __launch_bounds__(512, 1) void crf_kernel(
    const int* __restrict__ masks,
    const int* __restrict__ target,
    const float* __restrict__ trans_g,
    float* __restrict__ out_dec,
    float* __restrict__ out_ll)
{
    extern __shared__ __align__(16) char smem[];

    const int tid = threadIdx.x;
    const int g = tid >> 8;          // 0..1
    const int lt = tid & 255;        // 0..255 within group
    const int b = blockIdx.x * 2 + g;

    char* gb = smem + g * GROUP_BYTES;
    float (*s_v)[64] = (float(*)[64])(gb + GOFF_V);
    float (*s_P)[64] = (float(*)[64])(gb + GOFF_P);
    float* s_red = (float*)(gb + GOFF_RED);
    int*   s_misc = (int*)(gb + GOFF_MISC);   // [0]=len_v [1]=len_f
    int*   s_path = (int*)(gb + GOFF_PATH);
    unsigned char* s_bp = (unsigned char*)(gb + GOFF_BP);
    float* s_tt = (float*)(smem + OFF_TT);

    const int barV = 1 + 2 * g;
    const int barF = 2 + 2 * g;
    const float* emisb = &g_emis[(size_t)b * TT * KK];

    if (lt < 128) {
        // ================= VITERBI: 4 warps, 2 threads per state ============
        if (lt < 32) {
            int acc = 0;
#pragma unroll
            for (int i = 0; i < 8; i++) acc += masks[b * TT + lt + 32 * i];
#pragma unroll
            for (int o = 16; o; o >>= 1) acc += __shfl_xor_sync(0xFFFFFFFFu, acc, o);
            if (lt == 0) s_misc[0] = acc;
        }

        const int j = lt >> 1;
        const int h = lt & 1;
        const int k0 = h * 32;

        // transposed transition matrix (both groups write identical data)
        for (int i = lt; i < 4096; i += 128) {
            int k = i >> 6, jj = i & 63;
            s_tt[jj * 68 + k] = trans_g[i];
        }
        float Tcol[32];
#pragma unroll
        for (int kk = 0; kk < 32; kk++)
            Tcol[kk] = trans_g[(k0 + kk) * KK + j];

        float e0 = emisb[j];
        float ecur[4];
#pragma unroll
        for (int i = 0; i < 4; i++) ecur[i] = emisb[(size_t)(1 + i) * KK + j];

        float prevV = e0;
        if (h == 0) s_v[0][j] = e0;
        barx(barV, 128);
        const int len = s_misc[0];
        int rbuf = 0;

        float pqm[8];
        float pbv = 0.f;
        int pvalid = 0;
        int pt = 0;

        for (int tb = 1; tb < TT; tb += 4) {
            float enext[4];
#pragma unroll
            for (int i = 0; i < 4; i++) {
                int tt = tb + 4 + i;
                enext[i] = (tt < TT) ? emisb[(size_t)tt * KK + j] : 0.f;
            }
#pragma unroll
            for (int i = 0; i < 4; i++) {
                const int t = tb + i;
                if (t >= TT) break;

                const int wbuf = (rbuf == 2) ? 0 : rbuf + 1;
                const int obuf = (wbuf == 2) ? 0 : wbuf + 1;

                const float4* V4 = (const float4*)&s_v[rbuf][k0];
                float4 v0 = V4[0], v1 = V4[1], v2 = V4[2], v3 = V4[3];
                float4 v4 = V4[4], v5 = V4[5], v6 = V4[6], v7 = V4[7];

                if (pvalid) {
                    int li = 255;
                    if (pvalid == 1) {
                        int qq = 8;
#pragma unroll
                        for (int m = 7; m >= 0; m--)
                            qq = (pqm[m] == pbv) ? m : qq;
                        if (qq < 8) {
                            int kq = k0 + qq * 4;
                            float4 vq = *(const float4*)&s_v[obuf][kq];
                            float4 tq = *(const float4*)&s_tt[j * 68 + kq];
                            float c0 = vq.x + tq.x, c1 = vq.y + tq.y;
                            float c2 = vq.z + tq.z, c3 = vq.w + tq.w;
                            li = kq + 3;
                            li = (c2 == pbv) ? kq + 2 : li;
                            li = (c1 == pbv) ? kq + 1 : li;
                            li = (c0 == pbv) ? kq : li;
                        }
                        int oi = __shfl_xor_sync(0xFFFFFFFFu, li, 1);
                        li = min(li, oi);
                    } else {
                        li = j;
                    }
                    if (h == 0) s_bp[(pt - 1) * KK + j] = (unsigned char)li;
                }

                float qm[8];
                {
                    float c0, c1, c2, c3;
                    c0 = v0.x + Tcol[0];  c1 = v0.y + Tcol[1];
                    c2 = v0.z + Tcol[2];  c3 = v0.w + Tcol[3];
                    qm[0] = fmaxf(fmaxf(c0, c1), fmaxf(c2, c3));
                    c0 = v1.x + Tcol[4];  c1 = v1.y + Tcol[5];
                    c2 = v1.z + Tcol[6];  c3 = v1.w + Tcol[7];
                    qm[1] = fmaxf(fmaxf(c0, c1), fmaxf(c2, c3));
                    c0 = v2.x + Tcol[8];  c1 = v2.y + Tcol[9];
                    c2 = v2.z + Tcol[10]; c3 = v2.w + Tcol[11];
                    qm[2] = fmaxf(fmaxf(c0, c1), fmaxf(c2, c3));
                    c0 = v3.x + Tcol[12]; c1 = v3.y + Tcol[13];
                    c2 = v3.z + Tcol[14]; c3 = v3.w + Tcol[15];
                    qm[3] = fmaxf(fmaxf(c0, c1), fmaxf(c2, c3));
                    c0 = v4.x + Tcol[16]; c1 = v4.y + Tcol[17];
                    c2 = v4.z + Tcol[18]; c3 = v4.w + Tcol[19];
                    qm[4] = fmaxf(fmaxf(c0, c1), fmaxf(c2, c3));
                    c0 = v5.x + Tcol[20]; c1 = v5.y + Tcol[21];
                    c2 = v5.z + Tcol[22]; c3 = v5.w + Tcol[23];
                    qm[5] = fmaxf(fmaxf(c0, c1), fmaxf(c2, c3));
                    c0 = v6.x + Tcol[24]; c1 = v6.y + Tcol[25];
                    c2 = v6.z + Tcol[26]; c3 = v6.w + Tcol[27];
                    qm[6] = fmaxf(fmaxf(c0, c1), fmaxf(c2, c3));
                    c0 = v7.x + Tcol[28]; c1 = v7.y + Tcol[29];
                    c2 = v7.z + Tcol[30]; c3 = v7.w + Tcol[31];
                    qm[7] = fmaxf(fmaxf(c0, c1), fmaxf(c2, c3));
                }
                float m0 = fmaxf(qm[0], qm[1]), m1 = fmaxf(qm[2], qm[3]);
                float m2 = fmaxf(qm[4], qm[5]), m3 = fmaxf(qm[6], qm[7]);
                float bv = fmaxf(fmaxf(m0, m1), fmaxf(m2, m3));
                bv = fmaxf(bv, __shfl_xor_sync(0xFFFFFFFFu, bv, 1));

                float newv = (t < len) ? (bv + ecur[i]) : prevV;
                if (h == 0) s_v[wbuf][j] = newv;
                prevV = newv;

#pragma unroll
                for (int m = 0; m < 8; m++) pqm[m] = qm[m];
                pbv = bv;
                pvalid = (t < len) ? 1 : 2;
                pt = t;

                barx(barV, 128);
                rbuf = wbuf;
            }
#pragma unroll
            for (int i = 0; i < 4; i++) ecur[i] = enext[i];
        }

        {   // final pending bp (t = 255)
            const int obuf = (rbuf == 0) ? 2 : rbuf - 1;
            int li = 255;
            if (pvalid == 1) {
                int qq = 8;
#pragma unroll
                for (int m = 7; m >= 0; m--)
                    qq = (pqm[m] == pbv) ? m : qq;
                if (qq < 8) {
                    int kq = k0 + qq * 4;
                    float4 vq = *(const float4*)&s_v[obuf][kq];
                    float4 tq = *(const float4*)&s_tt[j * 68 + kq];
                    float c0 = vq.x + tq.x, c1 = vq.y + tq.y;
                    float c2 = vq.z + tq.z, c3 = vq.w + tq.w;
                    li = kq + 3;
                    li = (c2 == pbv) ? kq + 2 : li;
                    li = (c1 == pbv) ? kq + 1 : li;
                    li = (c0 == pbv) ? kq : li;
                }
                int oi = __shfl_xor_sync(0xFFFFFFFFu, li, 1);
                li = min(li, oi);
            } else {
                li = j;
            }
            if (h == 0) s_bp[(pt - 1) * KK + j] = (unsigned char)li;
        }
        barx(barV, 128);

        if (lt == 0) {
            float bvv = s_v[rbuf][0];
            int tg = 0;
#pragma unroll
            for (int k = 1; k < KK; k++)
                if (s_v[rbuf][k] > bvv) { bvv = s_v[rbuf][k]; tg = k; }
            s_path[TT - 1] = tg;
            for (int t = TT - 1; t >= 1; t--) {
                tg = s_bp[(t - 1) * KK + tg];
                s_path[t - 1] = tg;
            }
        }
        barx(barV, 128);
#pragma unroll
        for (int i = 0; i < 2; i++) {
            int tt = lt + 128 * i;
            out_dec[(size_t)b * TT + tt] = (float)((tt < len) ? s_path[tt] : 0);
        }

    } else {
        // ============ FORWARD: 4 warps (lt 128..255), 2 threads/state ======
        const int ft = lt - 128;

        if (ft < 32) {
            int acc = 0;
#pragma unroll
            for (int i = 0; i < 8; i++) acc += masks[b * TT + ft + 32 * i];
#pragma unroll
            for (int o = 16; o; o >>= 1) acc += __shfl_xor_sync(0xFFFFFFFFu, acc, o);
            if (ft == 0) s_misc[1] = acc;
        }

        const int j = ft >> 1;
        const int h = ft & 1;
        const int k0 = h * 32;

        u64t E2[16];
#pragma unroll
        for (int m = 0; m < 16; m++) {
            float t0 = trans_g[(k0 + 2 * m) * KK + j];
            float t1 = trans_g[(k0 + 2 * m + 1) * KK + j];
            E2[m] = pack2(expf(t0), expf(t1));
        }

        float e0 = emisb[j];
        float ecur[4];
#pragma unroll
        for (int i = 0; i < 4; i++) ecur[i] = emisb[(size_t)(1 + i) * KK + j];

        float prevP = __expf(e0);
        int iexp = 0;
        if (h == 0) s_P[0][j] = prevP;
        barx(barF, 128);
        const int len = s_misc[1];
        int buf = 0;

        for (int tb = 1; tb < TT; tb += 4) {
            float enext[4];
#pragma unroll
            for (int i = 0; i < 4; i++) {
                int tt = tb + 4 + i;
                enext[i] = (tt < TT) ? emisb[(size_t)tt * KK + j] : 0.f;
            }
            float eexp[4];
#pragma unroll
            for (int i = 0; i < 4; i++) eexp[i] = __expf(ecur[i]);

#pragma unroll
            for (int i = 0; i < 4; i++) {
                const int t = tb + i;
                if (t >= TT) break;

                float p0 = s_P[buf][0];
                const u64t* P2 = (const u64t*)&s_P[buf][k0];
                u64t s0 = 0ull, s1 = 0ull, s2 = 0ull, s3 = 0ull;
#pragma unroll
                for (int m = 0; m < 4; m++) {
                    s0 = ffma2(P2[4 * m + 0], E2[4 * m + 0], s0);
                    s1 = ffma2(P2[4 * m + 1], E2[4 * m + 1], s1);
                    s2 = ffma2(P2[4 * m + 2], E2[4 * m + 2], s2);
                    s3 = ffma2(P2[4 * m + 3], E2[4 * m + 3], s3);
                }
                float l0, h0, l1, h1, l2, h2, l3, h3;
                unpack2(s0, &l0, &h0);
                unpack2(s1, &l1, &h1);
                unpack2(s2, &l2, &h2);
                unpack2(s3, &l3, &h3);
                float S = ((l0 + h0) + (l1 + h1)) + ((l2 + h2) + (l3 + h3));
                S += __shfl_xor_sync(0xFFFFFFFFu, S, 1);

                int e0i = (int)(__float_as_uint(p0) >> 23);
                float scale = __uint_as_float((unsigned)(254 - e0i) << 23);
                if (t < len) {
                    prevP = S * scale * eexp[i];
                    iexp += e0i - 127;
                }
                if (h == 0) s_P[buf ^ 1][j] = prevP;
                barx(barF, 128);
                buf ^= 1;
            }
#pragma unroll
            for (int i = 0; i < 4; i++) ecur[i] = enext[i];
        }

        float sp = (h == 0) ? prevP : 0.f;
#pragma unroll
        for (int o = 16; o; o >>= 1) sp += __shfl_xor_sync(0xFFFFFFFFu, sp, o);
        if ((ft & 31) == 0) s_red[ft >> 5] = sp;

        float uacc = 0.f;
#pragma unroll
        for (int i = 0; i < 2; i++) {
            int tt = ft + 128 * i;
            if (tt < len) {
                int tg = target[b * TT + tt];
                uacc += emisb[(size_t)tt * KK + tg];
                if (tt >= 1) uacc += trans_g[target[b * TT + tt - 1] * KK + tg];
            }
        }
#pragma unroll
        for (int o = 16; o; o >>= 1) uacc += __shfl_xor_sync(0xFFFFFFFFu, uacc, o);
        if ((ft & 31) == 0) s_red[4 + (ft >> 5)] = uacc;
        barx(barF, 128);

        if (ft == 0) {
            float sumP = s_red[0] + s_red[1] + s_red[2] + s_red[3];
            float score = s_red[4] + s_red[5] + s_red[6] + s_red[7];
            const float LN2 = 0.69314718055994531f;
            out_ll[b] = score - ((float)iexp * LN2 + logf(sumP));
        }
    }
}

// ---------------------------------------------------------------------------
extern "C" void kernel_launch(void* const* d_in, const int* in_sizes, int n_in,
                              void* d_out, int out_size) {
    const float* hidden = (const float*)d_in[0];
    const int*   masks  = (const int*)d_in[1];
    const int*   target = (const int*)d_in[2];
    const float* Wm     = (const float*)d_in[3];
    const float* bias   = (const float*)d_in[4];
    const float* trans  = (const float*)d_in[5];
    float* out = (float*)d_out;

    gemm_emis_kernel<<<BB * TT / 128, 256>>>(hidden, Wm, bias);
    cudaFuncSetAttribute(crf_kernel,
                         cudaFuncAttributeMaxDynamicSharedMemorySize, SMEM_BYTES);
    crf_kernel<<<BB / 2, 512, SMEM_BYTES>>>(masks, target, trans,
                                            out, out + (size_t)BB * TT);
}

// round 15
// speedup vs baseline: 1.2292x; 1.2292x over previous
#include <cuda_runtime.h>
#include <cuda_bf16.h>
#include <math.h>

#define BB 128
#define TT 256
#define HH 768
#define KK 64

typedef unsigned long long u64t;

__device__ float g_emis[BB * TT * KK];   // emissions scratch, 8 MB

// ---- packed f32x2 helpers ------------------------------------------------
__device__ __forceinline__ u64t ffma2(u64t a, u64t b, u64t c) {
    u64t d;
    asm("fma.rn.f32x2 %0, %1, %2, %3;" : "=l"(d) : "l"(a), "l"(b), "l"(c));
    return d;
}
__device__ __forceinline__ u64t add2(u64t a, u64t b) {
    u64t d;
    asm("add.rn.f32x2 %0, %1, %2;" : "=l"(d) : "l"(a), "l"(b));
    return d;
}
__device__ __forceinline__ u64t pack2(float lo, float hi) {
    u64t d;
    unsigned a = __float_as_uint(lo), b = __float_as_uint(hi);
    asm("mov.b64 %0, {%1, %2};" : "=l"(d) : "r"(a), "r"(b));
    return d;
}
__device__ __forceinline__ void unpack2(u64t v, float* lo, float* hi) {
    unsigned a, b;
    asm("mov.b64 {%0, %1}, %2;" : "=r"(a), "=r"(b) : "l"(v));
    *lo = __uint_as_float(a);
    *hi = __uint_as_float(b);
}

// ---------------------------------------------------------------------------
// Kernel 1: emissions = hidden @ W + b (round-8 verbatim; ~FFMA2 floor)
// ---------------------------------------------------------------------------
__global__ __launch_bounds__(256) void gemm_emis_kernel(
    const float* __restrict__ A,
    const float* __restrict__ Wm,
    const float* __restrict__ bias)
{
    __shared__ float As[16][132];
    __shared__ float Bs[16][64];

    const int tid = threadIdx.x;
    const int m0 = blockIdx.x * 128;
    const int ty = tid >> 4;
    const int tx = tid & 15;

    u64t acc2[4][4];
#pragma unroll
    for (int rp = 0; rp < 4; rp++)
#pragma unroll
        for (int c = 0; c < 4; c++) acc2[rp][c] = 0ull;

    const int arow0 = (tid) >> 2,       ac40 = (tid) & 3;
    const int arow1 = (tid + 256) >> 2, ac41 = (tid + 256) & 3;
    const int brow = tid >> 4, bc4 = tid & 15;

    float4 aReg0 = *(const float4*)&A[(size_t)(m0 + arow0) * HH + ac40 * 4];
    float4 aReg1 = *(const float4*)&A[(size_t)(m0 + arow1) * HH + ac41 * 4];
    float4 bReg  = *(const float4*)&Wm[(size_t)(brow) * KK + bc4 * 4];

    for (int kt = 0; kt < HH; kt += 16) {
        As[ac40 * 4 + 0][arow0] = aReg0.x;
        As[ac40 * 4 + 1][arow0] = aReg0.y;
        As[ac40 * 4 + 2][arow0] = aReg0.z;
        As[ac40 * 4 + 3][arow0] = aReg0.w;
        As[ac41 * 4 + 0][arow1] = aReg1.x;
        As[ac41 * 4 + 1][arow1] = aReg1.y;
        As[ac41 * 4 + 2][arow1] = aReg1.z;
        As[ac41 * 4 + 3][arow1] = aReg1.w;
        *(float4*)&Bs[brow][bc4 * 4] = bReg;
        __syncthreads();

        if (kt + 16 < HH) {
            aReg0 = *(const float4*)&A[(size_t)(m0 + arow0) * HH + kt + 16 + ac40 * 4];
            aReg1 = *(const float4*)&A[(size_t)(m0 + arow1) * HH + kt + 16 + ac41 * 4];
            bReg  = *(const float4*)&Wm[(size_t)(kt + 16 + brow) * KK + bc4 * 4];
        }

#pragma unroll
        for (int kk = 0; kk < 16; kk++) {
            const u64t* ap = (const u64t*)&As[kk][ty * 8];
            u64t a2[4];
#pragma unroll
            for (int rp = 0; rp < 4; rp++) a2[rp] = ap[rp];
            float4 bv = *(const float4*)&Bs[kk][tx * 4];
            u64t bd[4];
            bd[0] = pack2(bv.x, bv.x);
            bd[1] = pack2(bv.y, bv.y);
            bd[2] = pack2(bv.z, bv.z);
            bd[3] = pack2(bv.w, bv.w);
#pragma unroll
            for (int rp = 0; rp < 4; rp++)
#pragma unroll
                for (int c = 0; c < 4; c++)
                    acc2[rp][c] = ffma2(a2[rp], bd[c], acc2[rp][c]);
        }
        __syncthreads();
    }

    float4 bb = *(const float4*)&bias[tx * 4];
    const float bbv[4] = {bb.x, bb.y, bb.z, bb.w};
#pragma unroll
    for (int rp = 0; rp < 4; rp++) {
        float o0[4], o1[4];
#pragma unroll
        for (int c = 0; c < 4; c++) {
            float lo, hi;
            unpack2(acc2[rp][c], &lo, &hi);
            o0[c] = lo + bbv[c];
            o1[c] = hi + bbv[c];
        }
        int row = m0 + ty * 8 + 2 * rp;
        *(float4*)&g_emis[(size_t)row * KK + tx * 4]       = make_float4(o0[0], o0[1], o0[2], o0[3]);
        *(float4*)&g_emis[(size_t)(row + 1) * KK + tx * 4] = make_float4(o1[0], o1[1], o1[2], o1[3]);
    }
}

// quad-max from a float4 of v and two packed Tcol pairs (bit-exact vs scalar)
#define QMAX(dst, vf, t01, t23)                                   \
    do {                                                          \
        u64t c01 = add2(pack2((vf).x, (vf).y), (t01));            \
        u64t c23 = add2(pack2((vf).z, (vf).w), (t23));            \
        float a0, a1, a2, a3;                                     \
        unpack2(c01, &a0, &a1);                                   \
        unpack2(c23, &a2, &a3);                                   \
        (dst) = fmaxf(fmaxf(a0, a1), fmaxf(a2, a3));              \
    } while (0)

// ---------------------------------------------------------------------------
// Kernel 2: CRF (round-8 structure + packed-f32x2 candidate adds).
// grid=128, 256 threads:
//   tid 0..127  : Viterbi, 2 threads/state, bar.sync 1,128
//   tid 128..255: forward log-norm + seq_score, bar.sync 2,128
// ---------------------------------------------------------------------------
__global__ __launch_bounds__(256) void crf_kernel(
    const int* __restrict__ masks,
    const int* __restrict__ target,
    const float* __restrict__ trans_g,
    float* __restrict__ out_dec,
    float* __restrict__ out_ll)
{
    __shared__ __align__(16) float s_v[3][64];
    __shared__ __align__(16) float s_P[2][64];
    __shared__ __align__(16) float s_tt[64 * 68];
    __shared__ float s_red[8];
    __shared__ int s_len_v, s_len_f;
    __shared__ int s_path[TT];
    __shared__ unsigned char s_bp[(TT - 1) * KK];

    const int tid = threadIdx.x;
    const int b = blockIdx.x;
    const float* emisb = &g_emis[(size_t)b * TT * KK];

    if (tid < 128) {
        // ================= VITERBI: 4 warps, 2 threads per state ============
        if (tid < 32) {
            int acc = 0;
#pragma unroll
            for (int i = 0; i < 8; i++) acc += masks[b * TT + tid + 32 * i];
#pragma unroll
            for (int o = 16; o; o >>= 1) acc += __shfl_xor_sync(0xFFFFFFFFu, acc, o);
            if (tid == 0) s_len_v = acc;
        }

        const int j = tid >> 1;
        const int h = tid & 1;
        const int k0 = h * 32;

        // transposed transition matrix: s_tt[j][k] = trans[k][j]
        for (int i = tid; i < 4096; i += 128) {
            int k = i >> 6, jj = i & 63;
            s_tt[jj * 68 + k] = trans_g[i];
        }
        // packed Tcol pairs: T2[m] = (Tcol[2m], Tcol[2m+1])
        u64t T2[16];
#pragma unroll
        for (int m = 0; m < 16; m++) {
            float t0 = trans_g[(k0 + 2 * m) * KK + j];
            float t1 = trans_g[(k0 + 2 * m + 1) * KK + j];
            T2[m] = pack2(t0, t1);
        }

        float e0 = emisb[j];
        float ecur[4];
#pragma unroll
        for (int i = 0; i < 4; i++) ecur[i] = emisb[(size_t)(1 + i) * KK + j];

        float prevV = e0;
        if (h == 0) s_v[0][j] = e0;
        asm volatile("bar.sync 1, 128;" ::: "memory");
        const int len = s_len_v;
        int rbuf = 0;

        float pqm[8];
        float pbv = 0.f;
        int pvalid = 0;
        int pt = 0;

        for (int tb = 1; tb < TT; tb += 4) {
            float enext[4];
#pragma unroll
            for (int i = 0; i < 4; i++) {
                int tt = tb + 4 + i;
                enext[i] = (tt < TT) ? emisb[(size_t)tt * KK + j] : 0.f;
            }
#pragma unroll
            for (int i = 0; i < 4; i++) {
                const int t = tb + i;
                if (t >= TT) break;

                const int wbuf = (rbuf == 2) ? 0 : rbuf + 1;
                const int obuf = (wbuf == 2) ? 0 : wbuf + 1;

                const float4* V4 = (const float4*)&s_v[rbuf][k0];
                float4 v0 = V4[0], v1 = V4[1], v2 = V4[2], v3 = V4[3];
                float4 v4 = V4[4], v5 = V4[5], v6 = V4[6], v7 = V4[7];

                if (pvalid) {
                    int li = 255;
                    if (pvalid == 1) {
                        int qq = 8;
#pragma unroll
                        for (int m = 7; m >= 0; m--)
                            qq = (pqm[m] == pbv) ? m : qq;
                        if (qq < 8) {
                            int kq = k0 + qq * 4;
                            float4 vq = *(const float4*)&s_v[obuf][kq];
                            float4 tq = *(const float4*)&s_tt[j * 68 + kq];
                            float c0 = vq.x + tq.x, c1 = vq.y + tq.y;
                            float c2 = vq.z + tq.z, c3 = vq.w + tq.w;
                            li = kq + 3;
                            li = (c2 == pbv) ? kq + 2 : li;
                            li = (c1 == pbv) ? kq + 1 : li;
                            li = (c0 == pbv) ? kq : li;
                        }
                        int oi = __shfl_xor_sync(0xFFFFFFFFu, li, 1);
                        li = min(li, oi);
                    } else {
                        li = j;
                    }
                    if (h == 0) s_bp[(pt - 1) * KK + j] = (unsigned char)li;
                }

                float qm[8];
                QMAX(qm[0], v0, T2[0],  T2[1]);
                QMAX(qm[1], v1, T2[2],  T2[3]);
                QMAX(qm[2], v2, T2[4],  T2[5]);
                QMAX(qm[3], v3, T2[6],  T2[7]);
                QMAX(qm[4], v4, T2[8],  T2[9]);
                QMAX(qm[5], v5, T2[10], T2[11]);
                QMAX(qm[6], v6, T2[12], T2[13]);
                QMAX(qm[7], v7, T2[14], T2[15]);

                float m0 = fmaxf(qm[0], qm[1]), m1 = fmaxf(qm[2], qm[3]);
                float m2 = fmaxf(qm[4], qm[5]), m3 = fmaxf(qm[6], qm[7]);
                float bv = fmaxf(fmaxf(m0, m1), fmaxf(m2, m3));
                bv = fmaxf(bv, __shfl_xor_sync(0xFFFFFFFFu, bv, 1));

                float newv = (t < len) ? (bv + ecur[i]) : prevV;
                if (h == 0) s_v[wbuf][j] = newv;
                prevV = newv;

#pragma unroll
                for (int m = 0; m < 8; m++) pqm[m] = qm[m];
                pbv = bv;
                pvalid = (t < len) ? 1 : 2;
                pt = t;

                asm volatile("bar.sync 1, 128;" ::: "memory");
                rbuf = wbuf;
            }
#pragma unroll
            for (int i = 0; i < 4; i++) ecur[i] = enext[i];
        }

        {   // final pending bp (t = 255)
            const int obuf = (rbuf == 0) ? 2 : rbuf - 1;
            int li = 255;
            if (pvalid == 1) {
                int qq = 8;
#pragma unroll
                for (int m = 7; m >= 0; m--)
                    qq = (pqm[m] == pbv) ? m : qq;
                if (qq < 8) {
                    int kq = k0 + qq * 4;
                    float4 vq = *(const float4*)&s_v[obuf][kq];
                    float4 tq = *(const float4*)&s_tt[j * 68 + kq];
                    float c0 = vq.x + tq.x, c1 = vq.y + tq.y;
                    float c2 = vq.z + tq.z, c3 = vq.w + tq.w;
                    li = kq + 3;
                    li = (c2 == pbv) ? kq + 2 : li;
                    li = (c1 == pbv) ? kq + 1 : li;
                    li = (c0 == pbv) ? kq : li;
                }
                int oi = __shfl_xor_sync(0xFFFFFFFFu, li, 1);
                li = min(li, oi);
            } else {
                li = j;
            }
            if (h == 0) s_bp[(pt - 1) * KK + j] = (unsigned char)li;
        }
        asm volatile("bar.sync 1, 128;" ::: "memory");

        if (tid == 0) {
            float bvv = s_v[rbuf][0];
            int tg = 0;
#pragma unroll
            for (int k = 1; k < KK; k++)
                if (s_v[rbuf][k] > bvv) { bvv = s_v[rbuf][k]; tg = k; }
            s_path[TT - 1] = tg;
            for (int t = TT - 1; t >= 1; t--) {
                tg = s_bp[(t - 1) * KK + tg];
                s_path[t - 1] = tg;
            }
        }
        asm volatile("bar.sync 1, 128;" ::: "memory");
#pragma unroll
        for (int i = 0; i < 2; i++) {
            int tt = tid + 128 * i;
            out_dec[(size_t)b * TT + tt] = (float)((tt < len) ? s_path[tt] : 0);
        }

    } else {
        // ============ FORWARD: 4 warps (tid 128..255), 2 threads/state ======
        const int ft = tid - 128;

        if (ft < 32) {
            int acc = 0;
#pragma unroll
            for (int i = 0; i < 8; i++) acc += masks[b * TT + ft + 32 * i];
#pragma unroll
            for (int o = 16; o; o >>= 1) acc += __shfl_xor_sync(0xFFFFFFFFu, acc, o);
            if (ft == 0) s_len_f = acc;
        }

        const int j = ft >> 1;
        const int h = ft & 1;
        const int k0 = h * 32;

        u64t E2[16];
#pragma unroll
        for (int m = 0; m < 16; m++) {
            float t0 = trans_g[(k0 + 2 * m) * KK + j];
            float t1 = trans_g[(k0 + 2 * m + 1) * KK + j];
            E2[m] = pack2(expf(t0), expf(t1));
        }

        float e0 = emisb[j];
        float ecur[4];
#pragma unroll
        for (int i = 0; i < 4; i++) ecur[i] = emisb[(size_t)(1 + i) * KK + j];

        float prevP = __expf(e0);
        int iexp = 0;
        if (h == 0) s_P[0][j] = prevP;
        asm volatile("bar.sync 2, 128;" ::: "memory");
        const int len = s_len_f;
        int buf = 0;

        for (int tb = 1; tb < TT; tb += 4) {
            float enext[4];
#pragma unroll
            for (int i = 0; i < 4; i++) {
                int tt = tb + 4 + i;
                enext[i] = (tt < TT) ? emisb[(size_t)tt * KK + j] : 0.f;
            }
            float eexp[4];
#pragma unroll
            for (int i = 0; i < 4; i++) eexp[i] = __expf(ecur[i]);

#pragma unroll
            for (int i = 0; i < 4; i++) {
                const int t = tb + i;
                if (t >= TT) break;

                float p0 = s_P[buf][0];
                const u64t* P2 = (const u64t*)&s_P[buf][k0];
                u64t s0 = 0ull, s1 = 0ull, s2 = 0ull, s3 = 0ull;
#pragma unroll
                for (int m = 0; m < 4; m++) {
                    s0 = ffma2(P2[4 * m + 0], E2[4 * m + 0], s0);
                    s1 = ffma2(P2[4 * m + 1], E2[4 * m + 1], s1);
                    s2 = ffma2(P2[4 * m + 2], E2[4 * m + 2], s2);
                    s3 = ffma2(P2[4 * m + 3], E2[4 * m + 3], s3);
                }
                // packed sum tree (order change only affects ll at ~1e-7)
                u64t t01 = add2(s0, s1);
                u64t t23 = add2(s2, s3);
                u64t tt2 = add2(t01, t23);
                float Slo, Shi;
                unpack2(tt2, &Slo, &Shi);
                float S = Slo + Shi;
                S += __shfl_xor_sync(0xFFFFFFFFu, S, 1);

                int e0i = (int)(__float_as_uint(p0) >> 23);
                float scale = __uint_as_float((unsigned)(254 - e0i) << 23);
                if (t < len) {
                    prevP = S * scale * eexp[i];
                    iexp += e0i - 127;
                }
                if (h == 0) s_P[buf ^ 1][j] = prevP;
                asm volatile("bar.sync 2, 128;" ::: "memory");
                buf ^= 1;
            }
#pragma unroll
            for (int i = 0; i < 4; i++) ecur[i] = enext[i];
        }

        float sp = (h == 0) ? prevP : 0.f;
#pragma unroll
        for (int o = 16; o; o >>= 1) sp += __shfl_xor_sync(0xFFFFFFFFu, sp, o);
        if ((ft & 31) == 0) s_red[ft >> 5] = sp;

        float uacc = 0.f;
#pragma unroll
        for (int i = 0; i < 2; i++) {
            int tt = ft + 128 * i;
            if (tt < len) {
                int tg = target[b * TT + tt];
                uacc += emisb[(size_t)tt * KK + tg];
                if (tt >= 1) uacc += trans_g[target[b * TT + tt - 1] * KK + tg];
            }
        }
#pragma unroll
        for (int o = 16; o; o >>= 1) uacc += __shfl_xor_sync(0xFFFFFFFFu, uacc, o);
        if ((ft & 31) == 0) s_red[4 + (ft >> 5)] = uacc;
        asm volatile("bar.sync 2, 128;" ::: "memory");

        if (ft == 0) {
            float sumP = s_red[0] + s_red[1] + s_red[2] + s_red[3];
            float score = s_red[4] + s_red[5] + s_red[6] + s_red[7];
            const float LN2 = 0.69314718055994531f;
            out_ll[b] = score - ((float)iexp * LN2 + logf(sumP));
        }
    }
}

// ---------------------------------------------------------------------------
extern "C" void kernel_launch(void* const* d_in, const int* in_sizes, int n_in,
                              void* d_out, int out_size) {
    const float* hidden = (const float*)d_in[0];
    const int*   masks  = (const int*)d_in[1];
    const int*   target = (const int*)d_in[2];
    const float* Wm     = (const float*)d_in[3];
    const float* bias   = (const float*)d_in[4];
    const float* trans  = (const float*)d_in[5];
    float* out = (float*)d_out;

    gemm_emis_kernel<<<BB * TT / 128, 256>>>(hidden, Wm, bias);
    crf_kernel<<<BB, 256>>>(masks, target, trans, out, out + (size_t)BB * TT);
}

// round 16
// speedup vs baseline: 1.3215x; 1.0751x over previous
#include <cuda_runtime.h>
#include <cuda_bf16.h>
#include <math.h>

#define BB 128
#define TT 256
#define HH 768
#define KK 64

typedef unsigned long long u64t;

__device__ float g_emis[BB * TT * KK];   // emissions scratch, 8 MB

// ---- packed f32x2 helpers ------------------------------------------------
__device__ __forceinline__ u64t ffma2(u64t a, u64t b, u64t c) {
    u64t d;
    asm("fma.rn.f32x2 %0, %1, %2, %3;" : "=l"(d) : "l"(a), "l"(b), "l"(c));
    return d;
}
__device__ __forceinline__ u64t add2(u64t a, u64t b) {
    u64t d;
    asm("add.rn.f32x2 %0, %1, %2;" : "=l"(d) : "l"(a), "l"(b));
    return d;
}
__device__ __forceinline__ u64t pack2(float lo, float hi) {
    u64t d;
    unsigned a = __float_as_uint(lo), b = __float_as_uint(hi);
    asm("mov.b64 %0, {%1, %2};" : "=l"(d) : "r"(a), "r"(b));
    return d;
}
__device__ __forceinline__ void unpack2(u64t v, float* lo, float* hi) {
    unsigned a, b;
    asm("mov.b64 {%0, %1}, %2;" : "=r"(a), "=r"(b) : "l"(v));
    *lo = __uint_as_float(a);
    *hi = __uint_as_float(b);
}

// ---------------------------------------------------------------------------
// Kernel 1: emissions = hidden @ W + b (round-8 verbatim; ~FFMA2 floor)
// ---------------------------------------------------------------------------
__global__ __launch_bounds__(256) void gemm_emis_kernel(
    const float* __restrict__ A,
    const float* __restrict__ Wm,
    const float* __restrict__ bias)
{
    __shared__ float As[16][132];
    __shared__ float Bs[16][64];

    const int tid = threadIdx.x;
    const int m0 = blockIdx.x * 128;
    const int ty = tid >> 4;
    const int tx = tid & 15;

    u64t acc2[4][4];
#pragma unroll
    for (int rp = 0; rp < 4; rp++)
#pragma unroll
        for (int c = 0; c < 4; c++) acc2[rp][c] = 0ull;

    const int arow0 = (tid) >> 2,       ac40 = (tid) & 3;
    const int arow1 = (tid + 256) >> 2, ac41 = (tid + 256) & 3;
    const int brow = tid >> 4, bc4 = tid & 15;

    float4 aReg0 = *(const float4*)&A[(size_t)(m0 + arow0) * HH + ac40 * 4];
    float4 aReg1 = *(const float4*)&A[(size_t)(m0 + arow1) * HH + ac41 * 4];
    float4 bReg  = *(const float4*)&Wm[(size_t)(brow) * KK + bc4 * 4];

    for (int kt = 0; kt < HH; kt += 16) {
        As[ac40 * 4 + 0][arow0] = aReg0.x;
        As[ac40 * 4 + 1][arow0] = aReg0.y;
        As[ac40 * 4 + 2][arow0] = aReg0.z;
        As[ac40 * 4 + 3][arow0] = aReg0.w;
        As[ac41 * 4 + 0][arow1] = aReg1.x;
        As[ac41 * 4 + 1][arow1] = aReg1.y;
        As[ac41 * 4 + 2][arow1] = aReg1.z;
        As[ac41 * 4 + 3][arow1] = aReg1.w;
        *(float4*)&Bs[brow][bc4 * 4] = bReg;
        __syncthreads();

        if (kt + 16 < HH) {
            aReg0 = *(const float4*)&A[(size_t)(m0 + arow0) * HH + kt + 16 + ac40 * 4];
            aReg1 = *(const float4*)&A[(size_t)(m0 + arow1) * HH + kt + 16 + ac41 * 4];
            bReg  = *(const float4*)&Wm[(size_t)(kt + 16 + brow) * KK + bc4 * 4];
        }

#pragma unroll
        for (int kk = 0; kk < 16; kk++) {
            const u64t* ap = (const u64t*)&As[kk][ty * 8];
            u64t a2[4];
#pragma unroll
            for (int rp = 0; rp < 4; rp++) a2[rp] = ap[rp];
            float4 bv = *(const float4*)&Bs[kk][tx * 4];
            u64t bd[4];
            bd[0] = pack2(bv.x, bv.x);
            bd[1] = pack2(bv.y, bv.y);
            bd[2] = pack2(bv.z, bv.z);
            bd[3] = pack2(bv.w, bv.w);
#pragma unroll
            for (int rp = 0; rp < 4; rp++)
#pragma unroll
                for (int c = 0; c < 4; c++)
                    acc2[rp][c] = ffma2(a2[rp], bd[c], acc2[rp][c]);
        }
        __syncthreads();
    }

    float4 bb = *(const float4*)&bias[tx * 4];
    const float bbv[4] = {bb.x, bb.y, bb.z, bb.w};
#pragma unroll
    for (int rp = 0; rp < 4; rp++) {
        float o0[4], o1[4];
#pragma unroll
        for (int c = 0; c < 4; c++) {
            float lo, hi;
            unpack2(acc2[rp][c], &lo, &hi);
            o0[c] = lo + bbv[c];
            o1[c] = hi + bbv[c];
        }
        int row = m0 + ty * 8 + 2 * rp;
        *(float4*)&g_emis[(size_t)row * KK + tx * 4]       = make_float4(o0[0], o0[1], o0[2], o0[3]);
        *(float4*)&g_emis[(size_t)(row + 1) * KK + tx * 4] = make_float4(o1[0], o1[1], o1[2], o1[3]);
    }
}

// quad-max from a float4 of v and two packed Tcol pairs (bit-exact vs scalar)
#define QMAX(dst, vf, t01, t23)                                   \
    do {                                                          \
        u64t c01 = add2(pack2((vf).x, (vf).y), (t01));            \
        u64t c23 = add2(pack2((vf).z, (vf).w), (t23));            \
        float a0, a1, a2, a3;                                     \
        unpack2(c01, &a0, &a1);                                   \
        unpack2(c23, &a2, &a3);                                   \
        (dst) = fmaxf(fmaxf(a0, a1), fmaxf(a2, a3));              \
    } while (0)

// ---------------------------------------------------------------------------
// Kernel 2: CRF. grid=128, 256 threads:
//   tid 0..127  : Viterbi, 2 threads/state, bar.sync 1,128
//     - pending-quad scan runs in the value-LDS shadow; recheck loads issue
//       early; resolve ALU after the value store; NO resolve shfl — both
//       halves store their candidate (255 sentinel) into s_bp2[255][128],
//       backtrack takes min of the pair (identical first-max semantics).
//   tid 128..255: forward log-norm + seq_score, bar.sync 2,128 (unchanged)
// s_bp2 lives in dynamic smem (32640 B).
// ---------------------------------------------------------------------------
__global__ __launch_bounds__(256) void crf_kernel(
    const int* __restrict__ masks,
    const int* __restrict__ target,
    const float* __restrict__ trans_g,
    float* __restrict__ out_dec,
    float* __restrict__ out_ll)
{
    extern __shared__ unsigned char s_bp2[];        // [255][128]
    __shared__ __align__(16) float s_v[3][64];
    __shared__ __align__(16) float s_P[2][64];
    __shared__ __align__(16) float s_tt[64 * 68];
    __shared__ float s_red[8];
    __shared__ int s_len_v, s_len_f;
    __shared__ int s_path[TT];

    const int tid = threadIdx.x;
    const int b = blockIdx.x;
    const float* emisb = &g_emis[(size_t)b * TT * KK];

    if (tid < 128) {
        // ================= VITERBI: 4 warps, 2 threads per state ============
        if (tid < 32) {
            int acc = 0;
#pragma unroll
            for (int i = 0; i < 8; i++) acc += masks[b * TT + tid + 32 * i];
#pragma unroll
            for (int o = 16; o; o >>= 1) acc += __shfl_xor_sync(0xFFFFFFFFu, acc, o);
            if (tid == 0) s_len_v = acc;
        }

        const int j = tid >> 1;
        const int h = tid & 1;
        const int k0 = h * 32;

        // transposed transition matrix: s_tt[j][k] = trans[k][j]
        for (int i = tid; i < 4096; i += 128) {
            int k = i >> 6, jj = i & 63;
            s_tt[jj * 68 + k] = trans_g[i];
        }
        // packed Tcol pairs: T2[m] = (Tcol[2m], Tcol[2m+1])
        u64t T2[16];
#pragma unroll
        for (int m = 0; m < 16; m++) {
            float t0 = trans_g[(k0 + 2 * m) * KK + j];
            float t1 = trans_g[(k0 + 2 * m + 1) * KK + j];
            T2[m] = pack2(t0, t1);
        }

        float e0 = emisb[j];
        float ecur[4];
#pragma unroll
        for (int i = 0; i < 4; i++) ecur[i] = emisb[(size_t)(1 + i) * KK + j];

        float prevV = e0;
        if (h == 0) s_v[0][j] = e0;
        asm volatile("bar.sync 1, 128;" ::: "memory");
        const int len = s_len_v;
        int rbuf = 0;

        float pqm[8];
        float pbv = 0.f;
        int pvalid = 0;      // 0=none, 1=resolve, 2=identity
        int pt = 0;

        for (int tb = 1; tb < TT; tb += 4) {
            float enext[4];
#pragma unroll
            for (int i = 0; i < 4; i++) {
                int tt = tb + 4 + i;
                enext[i] = (tt < TT) ? emisb[(size_t)tt * KK + j] : 0.f;
            }
#pragma unroll
            for (int i = 0; i < 4; i++) {
                const int t = tb + i;
                if (t >= TT) break;

                const int wbuf = (rbuf == 2) ? 0 : rbuf + 1;
                const int obuf = (wbuf == 2) ? 0 : wbuf + 1;   // = (rbuf+2)%3

                // ---- value-phase loads first ----
                const float4* V4 = (const float4*)&s_v[rbuf][k0];
                float4 v0 = V4[0], v1 = V4[1], v2 = V4[2], v3 = V4[3];
                float4 v4 = V4[4], v5 = V4[5], v6 = V4[6], v7 = V4[7];

                // ---- pending-quad scan (register-only, in LDS shadow) ----
                int qq = 8;
#pragma unroll
                for (int m = 7; m >= 0; m--)
                    qq = (pqm[m] == pbv) ? m : qq;      // first quad wins
                int kq = k0 + ((qq == 8) ? 0 : qq) * 4;
                // recheck loads (old buffer stable; address safe even if unused)
                float4 vq = *(const float4*)&s_v[obuf][kq];
                float4 tq = *(const float4*)&s_tt[j * 68 + kq];

                // ---- value phase ----
                float qm[8];
                QMAX(qm[0], v0, T2[0],  T2[1]);
                QMAX(qm[1], v1, T2[2],  T2[3]);
                QMAX(qm[2], v2, T2[4],  T2[5]);
                QMAX(qm[3], v3, T2[6],  T2[7]);
                QMAX(qm[4], v4, T2[8],  T2[9]);
                QMAX(qm[5], v5, T2[10], T2[11]);
                QMAX(qm[6], v6, T2[12], T2[13]);
                QMAX(qm[7], v7, T2[14], T2[15]);

                float m0 = fmaxf(qm[0], qm[1]), m1 = fmaxf(qm[2], qm[3]);
                float m2 = fmaxf(qm[4], qm[5]), m3 = fmaxf(qm[6], qm[7]);
                float bv = fmaxf(fmaxf(m0, m1), fmaxf(m2, m3));
                bv = fmaxf(bv, __shfl_xor_sync(0xFFFFFFFFu, bv, 1));

                float newv = (t < len) ? (bv + ecur[i]) : prevV;
                if (h == 0) s_v[wbuf][j] = newv;
                prevV = newv;

                // ---- resolve ALU (off the store->barrier edge; no shfl) ----
                if (pvalid) {
                    int li = 255;
                    if (pvalid == 1) {
                        if (qq < 8) {
                            float c0 = vq.x + tq.x, c1 = vq.y + tq.y;
                            float c2 = vq.z + tq.z, c3 = vq.w + tq.w;
                            li = (c3 == pbv) ? kq + 3 : li;
                            li = (c2 == pbv) ? kq + 2 : li;
                            li = (c1 == pbv) ? kq + 1 : li;
                            li = (c0 == pbv) ? kq : li;
                        }
                    } else {
                        li = j;
                    }
                    s_bp2[(pt - 1) * 128 + (j << 1) + h] = (unsigned char)li;
                }

                // ---- stash pending ----
#pragma unroll
                for (int m = 0; m < 8; m++) pqm[m] = qm[m];
                pbv = bv;
                pvalid = (t < len) ? 1 : 2;
                pt = t;

                asm volatile("bar.sync 1, 128;" ::: "memory");
                rbuf = wbuf;
            }
#pragma unroll
            for (int i = 0; i < 4; i++) ecur[i] = enext[i];
        }

        {   // final pending bp (t = 255); old buffer = predecessor of rbuf
            const int obuf = (rbuf == 0) ? 2 : rbuf - 1;
            int li = 255;
            if (pvalid == 1) {
                int qq = 8;
#pragma unroll
                for (int m = 7; m >= 0; m--)
                    qq = (pqm[m] == pbv) ? m : qq;
                if (qq < 8) {
                    int kq = k0 + qq * 4;
                    float4 vq = *(const float4*)&s_v[obuf][kq];
                    float4 tq = *(const float4*)&s_tt[j * 68 + kq];
                    float c0 = vq.x + tq.x, c1 = vq.y + tq.y;
                    float c2 = vq.z + tq.z, c3 = vq.w + tq.w;
                    li = (c3 == pbv) ? kq + 3 : li;
                    li = (c2 == pbv) ? kq + 2 : li;
                    li = (c1 == pbv) ? kq + 1 : li;
                    li = (c0 == pbv) ? kq : li;
                }
            } else {
                li = j;
            }
            s_bp2[(pt - 1) * 128 + (j << 1) + h] = (unsigned char)li;
        }
        asm volatile("bar.sync 1, 128;" ::: "memory");

        if (tid == 0) {
            float bvv = s_v[rbuf][0];
            int tg = 0;
#pragma unroll
            for (int k = 1; k < KK; k++)
                if (s_v[rbuf][k] > bvv) { bvv = s_v[rbuf][k]; tg = k; }
            s_path[TT - 1] = tg;
            for (int t = TT - 1; t >= 1; t--) {
                int a = s_bp2[(t - 1) * 128 + (tg << 1)];
                int c = s_bp2[(t - 1) * 128 + (tg << 1) + 1];
                tg = min(a, c);
                s_path[t - 1] = tg;
            }
        }
        asm volatile("bar.sync 1, 128;" ::: "memory");
#pragma unroll
        for (int i = 0; i < 2; i++) {
            int tt = tid + 128 * i;
            out_dec[(size_t)b * TT + tt] = (float)((tt < len) ? s_path[tt] : 0);
        }

    } else {
        // ============ FORWARD: 4 warps (tid 128..255), 2 threads/state ======
        const int ft = tid - 128;

        if (ft < 32) {
            int acc = 0;
#pragma unroll
            for (int i = 0; i < 8; i++) acc += masks[b * TT + ft + 32 * i];
#pragma unroll
            for (int o = 16; o; o >>= 1) acc += __shfl_xor_sync(0xFFFFFFFFu, acc, o);
            if (ft == 0) s_len_f = acc;
        }

        const int j = ft >> 1;
        const int h = ft & 1;
        const int k0 = h * 32;

        u64t E2[16];
#pragma unroll
        for (int m = 0; m < 16; m++) {
            float t0 = trans_g[(k0 + 2 * m) * KK + j];
            float t1 = trans_g[(k0 + 2 * m + 1) * KK + j];
            E2[m] = pack2(expf(t0), expf(t1));
        }

        float e0 = emisb[j];
        float ecur[4];
#pragma unroll
        for (int i = 0; i < 4; i++) ecur[i] = emisb[(size_t)(1 + i) * KK + j];

        float prevP = __expf(e0);
        int iexp = 0;
        if (h == 0) s_P[0][j] = prevP;
        asm volatile("bar.sync 2, 128;" ::: "memory");
        const int len = s_len_f;
        int buf = 0;

        for (int tb = 1; tb < TT; tb += 4) {
            float enext[4];
#pragma unroll
            for (int i = 0; i < 4; i++) {
                int tt = tb + 4 + i;
                enext[i] = (tt < TT) ? emisb[(size_t)tt * KK + j] : 0.f;
            }
            float eexp[4];
#pragma unroll
            for (int i = 0; i < 4; i++) eexp[i] = __expf(ecur[i]);

#pragma unroll
            for (int i = 0; i < 4; i++) {
                const int t = tb + i;
                if (t >= TT) break;

                float p0 = s_P[buf][0];
                const u64t* P2 = (const u64t*)&s_P[buf][k0];
                u64t s0 = 0ull, s1 = 0ull, s2 = 0ull, s3 = 0ull;
#pragma unroll
                for (int m = 0; m < 4; m++) {
                    s0 = ffma2(P2[4 * m + 0], E2[4 * m + 0], s0);
                    s1 = ffma2(P2[4 * m + 1], E2[4 * m + 1], s1);
                    s2 = ffma2(P2[4 * m + 2], E2[4 * m + 2], s2);
                    s3 = ffma2(P2[4 * m + 3], E2[4 * m + 3], s3);
                }
                u64t t01 = add2(s0, s1);
                u64t t23 = add2(s2, s3);
                u64t tt2 = add2(t01, t23);
                float Slo, Shi;
                unpack2(tt2, &Slo, &Shi);
                float S = Slo + Shi;
                S += __shfl_xor_sync(0xFFFFFFFFu, S, 1);

                int e0i = (int)(__float_as_uint(p0) >> 23);
                float scale = __uint_as_float((unsigned)(254 - e0i) << 23);
                if (t < len) {
                    prevP = S * scale * eexp[i];
                    iexp += e0i - 127;
                }
                if (h == 0) s_P[buf ^ 1][j] = prevP;
                asm volatile("bar.sync 2, 128;" ::: "memory");
                buf ^= 1;
            }
#pragma unroll
            for (int i = 0; i < 4; i++) ecur[i] = enext[i];
        }

        float sp = (h == 0) ? prevP : 0.f;
#pragma unroll
        for (int o = 16; o; o >>= 1) sp += __shfl_xor_sync(0xFFFFFFFFu, sp, o);
        if ((ft & 31) == 0) s_red[ft >> 5] = sp;

        float uacc = 0.f;
#pragma unroll
        for (int i = 0; i < 2; i++) {
            int tt = ft + 128 * i;
            if (tt < len) {
                int tg = target[b * TT + tt];
                uacc += emisb[(size_t)tt * KK + tg];
                if (tt >= 1) uacc += trans_g[target[b * TT + tt - 1] * KK + tg];
            }
        }
#pragma unroll
        for (int o = 16; o; o >>= 1) uacc += __shfl_xor_sync(0xFFFFFFFFu, uacc, o);
        if ((ft & 31) == 0) s_red[4 + (ft >> 5)] = uacc;
        asm volatile("bar.sync 2, 128;" ::: "memory");

        if (ft == 0) {
            float sumP = s_red[0] + s_red[1] + s_red[2] + s_red[3];
            float score = s_red[4] + s_red[5] + s_red[6] + s_red[7];
            const float LN2 = 0.69314718055994531f;
            out_ll[b] = score - ((float)iexp * LN2 + logf(sumP));
        }
    }
}

// ---------------------------------------------------------------------------
extern "C" void kernel_launch(void* const* d_in, const int* in_sizes, int n_in,
                              void* d_out, int out_size) {
    const float* hidden = (const float*)d_in[0];
    const int*   masks  = (const int*)d_in[1];
    const int*   target = (const int*)d_in[2];
    const float* Wm     = (const float*)d_in[3];
    const float* bias   = (const float*)d_in[4];
    const float* trans  = (const float*)d_in[5];
    float* out = (float*)d_out;

    const int DYN = (TT - 1) * 128;   // 32640 B backpointer pairs
    gemm_emis_kernel<<<BB * TT / 128, 256>>>(hidden, Wm, bias);
    cudaFuncSetAttribute(crf_kernel,
                         cudaFuncAttributeMaxDynamicSharedMemorySize, DYN);
    crf_kernel<<<BB, 256, DYN>>>(masks, target, trans, out, out + (size_t)BB * TT);
}

// round 17
// speedup vs baseline: 1.4002x; 1.0595x over previous
#include <cuda_runtime.h>
#include <cuda_bf16.h>
#include <math.h>

#define BB 128
#define TT 256
#define HH 768
#define KK 64

typedef unsigned long long u64t;

__device__ float g_emis[BB * TT * KK];   // emissions scratch, 8 MB

// ---- packed f32x2 helpers ------------------------------------------------
__device__ __forceinline__ u64t ffma2(u64t a, u64t b, u64t c) {
    u64t d;
    asm("fma.rn.f32x2 %0, %1, %2, %3;" : "=l"(d) : "l"(a), "l"(b), "l"(c));
    return d;
}
__device__ __forceinline__ u64t add2(u64t a, u64t b) {
    u64t d;
    asm("add.rn.f32x2 %0, %1, %2;" : "=l"(d) : "l"(a), "l"(b));
    return d;
}
__device__ __forceinline__ u64t pack2(float lo, float hi) {
    u64t d;
    unsigned a = __float_as_uint(lo), b = __float_as_uint(hi);
    asm("mov.b64 %0, {%1, %2};" : "=l"(d) : "r"(a), "r"(b));
    return d;
}
__device__ __forceinline__ void unpack2(u64t v, float* lo, float* hi) {
    unsigned a, b;
    asm("mov.b64 {%0, %1}, %2;" : "=r"(a), "=r"(b) : "l"(v));
    *lo = __uint_as_float(a);
    *hi = __uint_as_float(b);
}

// ---------------------------------------------------------------------------
// Kernel 1: emissions = hidden @ W + b (unchanged; ~FFMA2 floor)
// ---------------------------------------------------------------------------
__global__ __launch_bounds__(256) void gemm_emis_kernel(
    const float* __restrict__ A,
    const float* __restrict__ Wm,
    const float* __restrict__ bias)
{
    __shared__ float As[16][132];
    __shared__ float Bs[16][64];

    const int tid = threadIdx.x;
    const int m0 = blockIdx.x * 128;
    const int ty = tid >> 4;
    const int tx = tid & 15;

    u64t acc2[4][4];
#pragma unroll
    for (int rp = 0; rp < 4; rp++)
#pragma unroll
        for (int c = 0; c < 4; c++) acc2[rp][c] = 0ull;

    const int arow0 = (tid) >> 2,       ac40 = (tid) & 3;
    const int arow1 = (tid + 256) >> 2, ac41 = (tid + 256) & 3;
    const int brow = tid >> 4, bc4 = tid & 15;

    float4 aReg0 = *(const float4*)&A[(size_t)(m0 + arow0) * HH + ac40 * 4];
    float4 aReg1 = *(const float4*)&A[(size_t)(m0 + arow1) * HH + ac41 * 4];
    float4 bReg  = *(const float4*)&Wm[(size_t)(brow) * KK + bc4 * 4];

    for (int kt = 0; kt < HH; kt += 16) {
        As[ac40 * 4 + 0][arow0] = aReg0.x;
        As[ac40 * 4 + 1][arow0] = aReg0.y;
        As[ac40 * 4 + 2][arow0] = aReg0.z;
        As[ac40 * 4 + 3][arow0] = aReg0.w;
        As[ac41 * 4 + 0][arow1] = aReg1.x;
        As[ac41 * 4 + 1][arow1] = aReg1.y;
        As[ac41 * 4 + 2][arow1] = aReg1.z;
        As[ac41 * 4 + 3][arow1] = aReg1.w;
        *(float4*)&Bs[brow][bc4 * 4] = bReg;
        __syncthreads();

        if (kt + 16 < HH) {
            aReg0 = *(const float4*)&A[(size_t)(m0 + arow0) * HH + kt + 16 + ac40 * 4];
            aReg1 = *(const float4*)&A[(size_t)(m0 + arow1) * HH + kt + 16 + ac41 * 4];
            bReg  = *(const float4*)&Wm[(size_t)(kt + 16 + brow) * KK + bc4 * 4];
        }

#pragma unroll
        for (int kk = 0; kk < 16; kk++) {
            const u64t* ap = (const u64t*)&As[kk][ty * 8];
            u64t a2[4];
#pragma unroll
            for (int rp = 0; rp < 4; rp++) a2[rp] = ap[rp];
            float4 bv = *(const float4*)&Bs[kk][tx * 4];
            u64t bd[4];
            bd[0] = pack2(bv.x, bv.x);
            bd[1] = pack2(bv.y, bv.y);
            bd[2] = pack2(bv.z, bv.z);
            bd[3] = pack2(bv.w, bv.w);
#pragma unroll
            for (int rp = 0; rp < 4; rp++)
#pragma unroll
                for (int c = 0; c < 4; c++)
                    acc2[rp][c] = ffma2(a2[rp], bd[c], acc2[rp][c]);
        }
        __syncthreads();
    }

    float4 bb = *(const float4*)&bias[tx * 4];
    const float bbv[4] = {bb.x, bb.y, bb.z, bb.w};
#pragma unroll
    for (int rp = 0; rp < 4; rp++) {
        float o0[4], o1[4];
#pragma unroll
        for (int c = 0; c < 4; c++) {
            float lo, hi;
            unpack2(acc2[rp][c], &lo, &hi);
            o0[c] = lo + bbv[c];
            o1[c] = hi + bbv[c];
        }
        int row = m0 + ty * 8 + 2 * rp;
        *(float4*)&g_emis[(size_t)row * KK + tx * 4]       = make_float4(o0[0], o0[1], o0[2], o0[3]);
        *(float4*)&g_emis[(size_t)(row + 1) * KK + tx * 4] = make_float4(o1[0], o1[1], o1[2], o1[3]);
    }
}

// quad-max from a float4 of v and two packed Tcol pairs (bit-exact vs scalar)
#define QMAX(dst, vf, t01, t23)                                   \
    do {                                                          \
        u64t c01 = add2(pack2((vf).x, (vf).y), (t01));            \
        u64t c23 = add2(pack2((vf).z, (vf).w), (t23));            \
        float a0, a1, a2, a3;                                     \
        unpack2(c01, &a0, &a1);                                   \
        unpack2(c23, &a2, &a3);                                   \
        (dst) = fmaxf(fmaxf(a0, a1), fmaxf(a2, a3));              \
    } while (0)

// ---------------------------------------------------------------------------
// Kernel 2: CRF. grid=128, 128 threads = 4 warps (1 per SMSP), NO shfl in
// either hot loop:
//   tid 0..63  : Viterbi, ONE thread per state (64 candidates in-register,
//                16 QMAX + fmax tree; deferred argmax over 16 quads, direct
//                s_bp store), bar.sync 1,64
//   tid 64..127: forward, ONE thread per state (32 FFMA2, packed sum tree),
//                bar.sync 2,64
// ---------------------------------------------------------------------------
__global__ __launch_bounds__(128) void crf_kernel(
    const int* __restrict__ masks,
    const int* __restrict__ target,
    const float* __restrict__ trans_g,
    float* __restrict__ out_dec,
    float* __restrict__ out_ll)
{
    __shared__ __align__(16) float s_v[3][64];
    __shared__ __align__(16) float s_P[2][64];
    __shared__ __align__(16) float s_tt[64 * 68];
    __shared__ float s_red[8];
    __shared__ int s_len_v, s_len_f;
    __shared__ int s_path[TT];
    __shared__ unsigned char s_bp[(TT - 1) * KK];

    const int tid = threadIdx.x;
    const int b = blockIdx.x;
    const float* emisb = &g_emis[(size_t)b * TT * KK];

    if (tid < 64) {
        // ============ VITERBI: 2 warps, 1 thread per state, no shfl =========
        const int j = tid;

        if (tid < 32) {
            int acc = 0;
#pragma unroll
            for (int i = 0; i < 8; i++) acc += masks[b * TT + tid + 32 * i];
#pragma unroll
            for (int o = 16; o; o >>= 1) acc += __shfl_xor_sync(0xFFFFFFFFu, acc, o);
            if (tid == 0) s_len_v = acc;
        }

        // transposed transition matrix: s_tt[j][k] = trans[k][j]
        for (int i = tid; i < 4096; i += 64) {
            int k = i >> 6, jj = i & 63;
            s_tt[jj * 68 + k] = trans_g[i];
        }
        // packed full column: T2[m] = (trans[2m][j], trans[2m+1][j])
        u64t T2[32];
#pragma unroll
        for (int m = 0; m < 32; m++) {
            float t0 = trans_g[(2 * m) * KK + j];
            float t1 = trans_g[(2 * m + 1) * KK + j];
            T2[m] = pack2(t0, t1);
        }

        float e0 = emisb[j];
        float ecur[4];
#pragma unroll
        for (int i = 0; i < 4; i++) ecur[i] = emisb[(size_t)(1 + i) * KK + j];

        float prevV = e0;
        s_v[0][j] = e0;
        asm volatile("bar.sync 1, 64;" ::: "memory");
        const int len = s_len_v;
        int rbuf = 0;

        float pqm[16];
        float pbv = 0.f;
        int pvalid = 0;      // 0=none, 1=resolve, 2=identity
        int pt = 0;

        for (int tb = 1; tb < TT; tb += 4) {
            float enext[4];
#pragma unroll
            for (int i = 0; i < 4; i++) {
                int tt = tb + 4 + i;
                enext[i] = (tt < TT) ? emisb[(size_t)tt * KK + j] : 0.f;
            }
#pragma unroll
            for (int i = 0; i < 4; i++) {
                const int t = tb + i;
                if (t >= TT) break;   // uniform

                const int wbuf = (rbuf == 2) ? 0 : rbuf + 1;
                const int obuf = (wbuf == 2) ? 0 : wbuf + 1;   // = (rbuf+2)%3

                // ---- value-phase loads first (16 LDS.128) ----
                const float4* V4 = (const float4*)&s_v[rbuf][0];
                float4 vv[16];
#pragma unroll
                for (int q = 0; q < 16; q++) vv[q] = V4[q];

                // ---- pending-quad scan in the LDS shadow ----
                int qq = 16;
#pragma unroll
                for (int m = 15; m >= 0; m--)
                    qq = (pqm[m] == pbv) ? m : qq;      // first quad wins
                int kq = ((qq == 16) ? 0 : qq) * 4;
                float4 vq = *(const float4*)&s_v[obuf][kq];
                float4 tq = *(const float4*)&s_tt[j * 68 + kq];

                // ---- value phase: 16 quad maxes + 4-level tree ----
                float qm[16];
#pragma unroll
                for (int q = 0; q < 16; q++)
                    QMAX(qm[q], vv[q], T2[2 * q], T2[2 * q + 1]);

                float n0 = fmaxf(qm[0], qm[1]),   n1 = fmaxf(qm[2], qm[3]);
                float n2 = fmaxf(qm[4], qm[5]),   n3 = fmaxf(qm[6], qm[7]);
                float n4 = fmaxf(qm[8], qm[9]),   n5 = fmaxf(qm[10], qm[11]);
                float n6 = fmaxf(qm[12], qm[13]), n7 = fmaxf(qm[14], qm[15]);
                n0 = fmaxf(n0, n1); n2 = fmaxf(n2, n3);
                n4 = fmaxf(n4, n5); n6 = fmaxf(n6, n7);
                float bv = fmaxf(fmaxf(n0, n2), fmaxf(n4, n6));

                float newv = (t < len) ? (bv + ecur[i]) : prevV;
                s_v[wbuf][j] = newv;
                prevV = newv;

                // ---- resolve previous step's backpointer (no shfl) ----
                if (pvalid) {
                    int li = 255;
                    if (pvalid == 1) {
                        if (qq < 16) {
                            float c0 = vq.x + tq.x, c1 = vq.y + tq.y;
                            float c2 = vq.z + tq.z, c3 = vq.w + tq.w;
                            li = (c3 == pbv) ? kq + 3 : li;
                            li = (c2 == pbv) ? kq + 2 : li;
                            li = (c1 == pbv) ? kq + 1 : li;
                            li = (c0 == pbv) ? kq : li;
                        }
                    } else {
                        li = j;
                    }
                    s_bp[(pt - 1) * KK + j] = (unsigned char)li;
                }

                // ---- stash pending ----
#pragma unroll
                for (int m = 0; m < 16; m++) pqm[m] = qm[m];
                pbv = bv;
                pvalid = (t < len) ? 1 : 2;
                pt = t;

                asm volatile("bar.sync 1, 64;" ::: "memory");
                rbuf = wbuf;
            }
#pragma unroll
            for (int i = 0; i < 4; i++) ecur[i] = enext[i];
        }

        {   // final pending bp (t = 255)
            const int obuf = (rbuf == 0) ? 2 : rbuf - 1;
            int li = 255;
            if (pvalid == 1) {
                int qq = 16;
#pragma unroll
                for (int m = 15; m >= 0; m--)
                    qq = (pqm[m] == pbv) ? m : qq;
                if (qq < 16) {
                    int kq = qq * 4;
                    float4 vq = *(const float4*)&s_v[obuf][kq];
                    float4 tq = *(const float4*)&s_tt[j * 68 + kq];
                    float c0 = vq.x + tq.x, c1 = vq.y + tq.y;
                    float c2 = vq.z + tq.z, c3 = vq.w + tq.w;
                    li = (c3 == pbv) ? kq + 3 : li;
                    li = (c2 == pbv) ? kq + 2 : li;
                    li = (c1 == pbv) ? kq + 1 : li;
                    li = (c0 == pbv) ? kq : li;
                }
            } else {
                li = j;
            }
            s_bp[(pt - 1) * KK + j] = (unsigned char)li;
        }
        asm volatile("bar.sync 1, 64;" ::: "memory");

        if (tid == 0) {
            float bvv = s_v[rbuf][0];
            int tg = 0;
#pragma unroll
            for (int k = 1; k < KK; k++)
                if (s_v[rbuf][k] > bvv) { bvv = s_v[rbuf][k]; tg = k; }
            s_path[TT - 1] = tg;
            for (int t = TT - 1; t >= 1; t--) {
                tg = s_bp[(t - 1) * KK + tg];
                s_path[t - 1] = tg;
            }
        }
        asm volatile("bar.sync 1, 64;" ::: "memory");
#pragma unroll
        for (int i = 0; i < 4; i++) {
            int tt = tid + 64 * i;
            out_dec[(size_t)b * TT + tt] = (float)((tt < len) ? s_path[tt] : 0);
        }

    } else {
        // ============ FORWARD: 2 warps, 1 thread per state, no shfl =========
        const int ft = tid - 64;     // 0..63
        const int j = ft;

        if (ft < 32) {
            int acc = 0;
#pragma unroll
            for (int i = 0; i < 8; i++) acc += masks[b * TT + ft + 32 * i];
#pragma unroll
            for (int o = 16; o; o >>= 1) acc += __shfl_xor_sync(0xFFFFFFFFu, acc, o);
            if (ft == 0) s_len_f = acc;
        }

        u64t E2[32];
#pragma unroll
        for (int m = 0; m < 32; m++) {
            float t0 = trans_g[(2 * m) * KK + j];
            float t1 = trans_g[(2 * m + 1) * KK + j];
            E2[m] = pack2(expf(t0), expf(t1));
        }

        float e0 = emisb[j];
        float ecur[4];
#pragma unroll
        for (int i = 0; i < 4; i++) ecur[i] = emisb[(size_t)(1 + i) * KK + j];

        float prevP = __expf(e0);
        int iexp = 0;
        s_P[0][j] = prevP;
        asm volatile("bar.sync 2, 64;" ::: "memory");
        const int len = s_len_f;
        int buf = 0;

        for (int tb = 1; tb < TT; tb += 4) {
            float enext[4];
#pragma unroll
            for (int i = 0; i < 4; i++) {
                int tt = tb + 4 + i;
                enext[i] = (tt < TT) ? emisb[(size_t)tt * KK + j] : 0.f;
            }
            float eexp[4];
#pragma unroll
            for (int i = 0; i < 4; i++) eexp[i] = __expf(ecur[i]);

#pragma unroll
            for (int i = 0; i < 4; i++) {
                const int t = tb + i;
                if (t >= TT) break;   // uniform

                float p0 = s_P[buf][0];
                const u64t* P2 = (const u64t*)&s_P[buf][0];
                u64t s0 = 0ull, s1 = 0ull, s2 = 0ull, s3 = 0ull;
#pragma unroll
                for (int m = 0; m < 8; m++) {
                    s0 = ffma2(P2[4 * m + 0], E2[4 * m + 0], s0);
                    s1 = ffma2(P2[4 * m + 1], E2[4 * m + 1], s1);
                    s2 = ffma2(P2[4 * m + 2], E2[4 * m + 2], s2);
                    s3 = ffma2(P2[4 * m + 3], E2[4 * m + 3], s3);
                }
                u64t t01 = add2(s0, s1);
                u64t t23 = add2(s2, s3);
                u64t tt2 = add2(t01, t23);
                float Slo, Shi;
                unpack2(tt2, &Slo, &Shi);
                float S = Slo + Shi;

                int e0i = (int)(__float_as_uint(p0) >> 23);
                float scale = __uint_as_float((unsigned)(254 - e0i) << 23);
                if (t < len) {
                    prevP = S * scale * eexp[i];
                    iexp += e0i - 127;
                }
                s_P[buf ^ 1][j] = prevP;
                asm volatile("bar.sync 2, 64;" ::: "memory");
                buf ^= 1;
            }
#pragma unroll
            for (int i = 0; i < 4; i++) ecur[i] = enext[i];
        }

        // log_norm: sum final P across 64 threads (2 warps)
        float sp = prevP;
#pragma unroll
        for (int o = 16; o; o >>= 1) sp += __shfl_xor_sync(0xFFFFFFFFu, sp, o);
        if ((ft & 31) == 0) s_red[ft >> 5] = sp;

        // seq_score partials: 4 t's per thread
        float uacc = 0.f;
#pragma unroll
        for (int i = 0; i < 4; i++) {
            int tt = ft + 64 * i;
            if (tt < len) {
                int tg = target[b * TT + tt];
                uacc += emisb[(size_t)tt * KK + tg];
                if (tt >= 1) uacc += trans_g[target[b * TT + tt - 1] * KK + tg];
            }
        }
#pragma unroll
        for (int o = 16; o; o >>= 1) uacc += __shfl_xor_sync(0xFFFFFFFFu, uacc, o);
        if ((ft & 31) == 0) s_red[4 + (ft >> 5)] = uacc;
        asm volatile("bar.sync 2, 64;" ::: "memory");

        if (ft == 0) {
            float sumP = s_red[0] + s_red[1];
            float score = s_red[4] + s_red[5];
            const float LN2 = 0.69314718055994531f;
            out_ll[b] = score - ((float)iexp * LN2 + logf(sumP));
        }
    }
}

// ---------------------------------------------------------------------------
extern "C" void kernel_launch(void* const* d_in, const int* in_sizes, int n_in,
                              void* d_out, int out_size) {
    const float* hidden = (const float*)d_in[0];
    const int*   masks  = (const int*)d_in[1];
    const int*   target = (const int*)d_in[2];
    const float* Wm     = (const float*)d_in[3];
    const float* bias   = (const float*)d_in[4];
    const float* trans  = (const float*)d_in[5];
    float* out = (float*)d_out;

    gemm_emis_kernel<<<BB * TT / 128, 256>>>(hidden, Wm, bias);
    crf_kernel<<<BB, 128>>>(masks, target, trans, out, out + (size_t)BB * TT);
}